// round 3
// baseline (speedup 1.0000x reference)
#include <cuda_runtime.h>
#include <cuda_bf16.h>
#include <cstdint>

#define DEV_INLINE __device__ __forceinline__

constexpr int Bb = 8;
constexpr int Nn = 4096;

// ---------------- static device scratch (no allocation) ----------------
__device__ float    g_h32[Bb * Nn * 64];          // h fp32 (8 MB)
__device__ unsigned g_hpk_hi[Bb * (Nn/2) * 64];   // h hi bf16, node-pair packed
__device__ unsigned g_hpk_lo[Bb * (Nn/2) * 64];   // h lo residual bf16

DEV_INLINE unsigned pack2(float f0, float f1) {   // f0 -> low 16 bits
    __nv_bfloat162 t = __floats2bfloat162_rn(f0, f1);
    return *reinterpret_cast<unsigned*>(&t);
}

// ============================================================================
// Kernel 1: h[b,n,j] = sum_{m,a} x[b,n,m,a]*W[m,p(j),a,w(j)]
// 512 threads: thread = (node, p). acc[16] -> no register spills.
// ============================================================================
__global__ void __launch_bounds__(512)
spconv_h_kernel(const float* __restrict__ x, const float* __restrict__ wgt)
{
    __shared__ float ws[128 * 64];   // ws[(m*32+a)*64 + j]
    const int t = threadIdx.x;
    const int b = blockIdx.y;
    const int node = blockIdx.x * 128 + (t >> 2);
    const int p = t & 3;

    for (int idx = t; idx < 128 * 64; idx += 512) {
        int ka = idx >> 6, j = idx & 63;
        int m = ka >> 5, a = ka & 31, pp = j >> 4, w = j & 15;
        ws[idx] = wgt[(((m * 4 + pp) * 32 + a) << 4) + w];
    }
    __syncthreads();

    float acc[16];
#pragma unroll
    for (int i = 0; i < 16; i++) acc[i] = 0.f;

    const float* xrow = x + (size_t)(b * Nn + node) * 128;
#pragma unroll 1
    for (int m = 0; m < 4; m++) {
#pragma unroll
        for (int a4 = 0; a4 < 8; a4++) {
            float4 xv = *(const float4*)(xrow + m * 32 + a4 * 4);
            float xs[4] = {xv.x, xv.y, xv.z, xv.w};
#pragma unroll
            for (int i = 0; i < 4; i++) {
                int a = a4 * 4 + i;
                const float4* wr = (const float4*)&ws[(m * 32 + a) * 64 + p * 16];
#pragma unroll
                for (int w4 = 0; w4 < 4; w4++) {
                    float4 wv = wr[w4];
                    acc[w4*4+0] = fmaf(xs[i], wv.x, acc[w4*4+0]);
                    acc[w4*4+1] = fmaf(xs[i], wv.y, acc[w4*4+1]);
                    acc[w4*4+2] = fmaf(xs[i], wv.z, acc[w4*4+2]);
                    acc[w4*4+3] = fmaf(xs[i], wv.w, acc[w4*4+3]);
                }
            }
        }
    }

    float* hp = g_h32 + (size_t)(b * Nn + node) * 64 + p * 16;
#pragma unroll
    for (int w4 = 0; w4 < 4; w4++)
        *(float4*)(hp + w4 * 4) = make_float4(acc[w4*4+0], acc[w4*4+1],
                                              acc[w4*4+2], acc[w4*4+3]);

    // pack node pairs: partner thread is +4 (same p, node+1)
    const size_t pbase = ((size_t)(b * 2048 + (node >> 1))) * 64 + p * 16;
    const bool even = ((t >> 2) & 1) == 0;
#pragma unroll 4
    for (int w = 0; w < 16; w++) {
        float v1 = __shfl_xor_sync(0xffffffffu, acc[w], 4);
        if (even) {
            float v0 = acc[w];
            __nv_bfloat16 h0 = __float2bfloat16_rn(v0);
            __nv_bfloat16 h1 = __float2bfloat16_rn(v1);
            g_hpk_hi[pbase + w] = (unsigned)__bfloat16_as_ushort(h0)
                                | ((unsigned)__bfloat16_as_ushort(h1) << 16);
            g_hpk_lo[pbase + w] = pack2(v0 - __bfloat162float(h0),
                                        v1 - __bfloat162float(h1));
        }
    }
}

// ============================================================================
// Kernel 2: per-batch C = adj @ h, fused rowsum/normalize/self-loop/relu/bias.
// 3-pass bf16 split. BM=64 BN=64 BK=32, 256 thr, 8 warps (2x4), warp tile
// 32x16. Double-buffered smem, ONE barrier per k-tile. 3 CTAs/SM.
// ============================================================================
constexpr int A_STR = 20;                 // u32 per A row (16 kpairs + 4 pad)
constexpr int B_STR = 72;                 // u32 per B kpair row (64 + 8 pad)
constexpr int A_STAGE = 64 * A_STR;       // 1280
constexpr int B_STAGE = 16 * B_STR;       // 1152
constexpr int OFF_AH = 0;                 // 2 stages
constexpr int OFF_AL = 2 * A_STAGE;       // 2560
constexpr int OFF_BH = 4 * A_STAGE;       // 5120
constexpr int OFF_BL = OFF_BH + 2 * B_STAGE;   // 7424
constexpr int OFF_RS = OFF_BL + 2 * B_STAGE;   // 9728  (64*5 floats)
constexpr int OFF_RI = OFF_RS + 320;           // 10048 (64 floats)
constexpr int SMEM_U32 = OFF_RI + 64;          // 10112
constexpr int SMEM_BYTES = SMEM_U32 * 4;       // 40448

DEV_INLINE void mma_bf16(float* c, const unsigned* a, const unsigned* b) {
    asm volatile(
        "mma.sync.aligned.m16n8k16.row.col.f32.bf16.bf16.f32 "
        "{%0,%1,%2,%3}, {%4,%5,%6,%7}, {%8,%9}, {%0,%1,%2,%3};\n"
        : "+f"(c[0]), "+f"(c[1]), "+f"(c[2]), "+f"(c[3])
        : "r"(a[0]), "r"(a[1]), "r"(a[2]), "r"(a[3]), "r"(b[0]), "r"(b[1]));
}

DEV_INLINE void ldsm4(unsigned* r, uint32_t addr) {
    asm volatile(
        "ldmatrix.sync.aligned.m8n8.x4.shared.b16 {%0,%1,%2,%3}, [%4];\n"
        : "=r"(r[0]), "=r"(r[1]), "=r"(r[2]), "=r"(r[3]) : "r"(addr));
}

__global__ void __launch_bounds__(256, 3)
spconv_gemm_kernel(const float* __restrict__ adj, const float* __restrict__ bias,
                   float* __restrict__ out)
{
    extern __shared__ unsigned sm[];
    const uint32_t smb = (uint32_t)__cvta_generic_to_shared(sm);

    const int t = threadIdx.x;
    const int lane = t & 31, warp = t >> 5;
    const int g = lane >> 2, tg = lane & 3;
    const int wrow = warp >> 2, wcol = warp & 3;      // 2 x 4 warp grid
    const int bx = blockIdx.x, b = blockIdx.y;

    const int lm_row = lane & 15;
    const int lm_kp  = (lane >> 4) * 4;

    // A staging: row = t&63, k-quarter = t>>6 (8 floats each)
    const int arow = t & 63, akq = t >> 6;
    const float* adj_base = adj + ((size_t)(b * Nn) + (size_t)bx * 64 + arow) * Nn + akq * 8;
    // B staging: kpair = t>>4, 4 u32 columns
    const int bkp = t >> 4, bn4 = (t & 15) * 4;
    const unsigned* hpH = g_hpk_hi + (size_t)b * 2048 * 64 + bkp * 64 + bn4;
    const unsigned* hpL = g_hpk_lo + (size_t)b * 2048 * 64 + bkp * 64 + bn4;

    float acc[2][2][4];
#pragma unroll
    for (int mf = 0; mf < 2; mf++)
#pragma unroll
        for (int nf = 0; nf < 2; nf++)
#pragma unroll
            for (int i = 0; i < 4; i++) acc[mf][nf][i] = 0.f;

    float rsum = 0.f;
    float4 va0, va1;
    uint4 vbh, vbl;

    auto ldgA = [&](int kt) {
        va0 = *(const float4*)(adj_base + kt * 32);
        va1 = *(const float4*)(adj_base + kt * 32 + 4);
    };
    auto ldgB = [&](int kt) {
        vbh = *(const uint4*)(hpH + (size_t)kt * 1024);
        vbl = *(const uint4*)(hpL + (size_t)kt * 1024);
    };
    auto stsAll = [&](int s) {
        unsigned* Ah = sm + OFF_AH + s * A_STAGE;
        unsigned* Al = sm + OFF_AL + s * A_STAGE;
        rsum += ((va0.x + va0.y) + (va0.z + va0.w))
              + ((va1.x + va1.y) + (va1.z + va1.w));
        __nv_bfloat16 c0 = __float2bfloat16_rn(va0.x);
        __nv_bfloat16 c1 = __float2bfloat16_rn(va0.y);
        __nv_bfloat16 c2 = __float2bfloat16_rn(va0.z);
        __nv_bfloat16 c3 = __float2bfloat16_rn(va0.w);
        __nv_bfloat16 c4 = __float2bfloat16_rn(va1.x);
        __nv_bfloat16 c5 = __float2bfloat16_rn(va1.y);
        __nv_bfloat16 c6 = __float2bfloat16_rn(va1.z);
        __nv_bfloat16 c7 = __float2bfloat16_rn(va1.w);
        unsigned h0 = (unsigned)__bfloat16_as_ushort(c0) | ((unsigned)__bfloat16_as_ushort(c1) << 16);
        unsigned h1 = (unsigned)__bfloat16_as_ushort(c2) | ((unsigned)__bfloat16_as_ushort(c3) << 16);
        unsigned h2 = (unsigned)__bfloat16_as_ushort(c4) | ((unsigned)__bfloat16_as_ushort(c5) << 16);
        unsigned h3 = (unsigned)__bfloat16_as_ushort(c6) | ((unsigned)__bfloat16_as_ushort(c7) << 16);
        unsigned l0 = pack2(va0.x - __bfloat162float(c0), va0.y - __bfloat162float(c1));
        unsigned l1 = pack2(va0.z - __bfloat162float(c2), va0.w - __bfloat162float(c3));
        unsigned l2 = pack2(va1.x - __bfloat162float(c4), va1.y - __bfloat162float(c5));
        unsigned l3 = pack2(va1.z - __bfloat162float(c6), va1.w - __bfloat162float(c7));
        int idx = arow * A_STR + akq * 4;
        *(uint2*)(Ah + idx)     = make_uint2(h0, h1);
        *(uint2*)(Ah + idx + 2) = make_uint2(h2, h3);
        *(uint2*)(Al + idx)     = make_uint2(l0, l1);
        *(uint2*)(Al + idx + 2) = make_uint2(l2, l3);
        *(uint4*)(sm + OFF_BH + s * B_STAGE + bkp * B_STR + bn4) = vbh;
        *(uint4*)(sm + OFF_BL + s * B_STAGE + bkp * B_STR + bn4) = vbl;
    };
    auto compute = [&](int s) {
        const unsigned* Bh = sm + OFF_BH + s * B_STAGE;
        const unsigned* Bl = sm + OFF_BL + s * B_STAGE;
        const uint32_t ahb = smb + (OFF_AH + s * A_STAGE) * 4;
        const uint32_t alb = smb + (OFF_AL + s * A_STAGE) * 4;
#pragma unroll
        for (int ks = 0; ks < 2; ks++) {
            unsigned bh[2][2], bl[2][2];
#pragma unroll
            for (int nf = 0; nf < 2; nf++) {
                int n = wcol * 16 + nf * 8 + g;
                int k0 = (ks * 8 + tg) * B_STR + n;
                bh[nf][0] = Bh[k0];  bh[nf][1] = Bh[k0 + 4 * B_STR];
                bl[nf][0] = Bl[k0];  bl[nf][1] = Bl[k0 + 4 * B_STR];
            }
#pragma unroll
            for (int mf = 0; mf < 2; mf++) {
                int aoff = ((wrow * 32 + mf * 16 + lm_row) * A_STR + ks * 8 + lm_kp) * 4;
                unsigned ah[4], al[4];
                ldsm4(ah, ahb + aoff);
                ldsm4(al, alb + aoff);
#pragma unroll
                for (int nf = 0; nf < 2; nf++) {
                    mma_bf16(acc[mf][nf], ah, bh[nf]);
                    mma_bf16(acc[mf][nf], al, bh[nf]);
                    mma_bf16(acc[mf][nf], ah, bl[nf]);
                }
            }
        }
    };

    // ---- pipeline: one barrier per k-tile ----
    ldgA(0); ldgB(0);
    stsAll(0);
    __syncthreads();
#pragma unroll 1
    for (int kt = 0; kt < 128; kt++) {
        const int cur = kt & 1;
        if (kt < 127) { ldgA(kt + 1); ldgB(kt + 1); }
        compute(cur);
        if (kt < 127) {
            stsAll(1 - cur);
            __syncthreads();
        }
    }

    // ---- rowsum reduce (dedicated smem region, no aliasing) ----
    float* rs   = (float*)(sm + OFF_RS);
    float* rinv = (float*)(sm + OFF_RI);
    rs[arow * 5 + akq] = rsum;
    __syncthreads();
    if (t < 64) {
        float s_ = 1.0f;  // self loop
#pragma unroll
        for (int q = 0; q < 4; q++) s_ += rs[t * 5 + q];
        rinv[t] = 1.0f / s_;
    }
    __syncthreads();

    // ---- epilogue: out = relu((S + h)*rinv) + bias ----
#pragma unroll
    for (int mf = 0; mf < 2; mf++) {
#pragma unroll
        for (int nf = 0; nf < 2; nf++) {
            int r0 = wrow * 32 + mf * 16 + g;
            int c  = wcol * 16 + nf * 8 + 2 * tg;
            float ri0 = rinv[r0], ri1 = rinv[r0 + 8];
            int gr0 = bx * 64 + r0;
            size_t o0 = ((size_t)(b * Nn + gr0)) * 64 + c;
            size_t o1 = o0 + (size_t)8 * 64;
            float2 h0 = *(const float2*)(g_h32 + o0);
            float2 h1 = *(const float2*)(g_h32 + o1);
            float bz0 = __ldg(bias + c), bz1 = __ldg(bias + c + 1);
            float2 w0, w1;
            w0.x = fmaxf((acc[mf][nf][0] + h0.x) * ri0, 0.f) + bz0;
            w0.y = fmaxf((acc[mf][nf][1] + h0.y) * ri0, 0.f) + bz1;
            w1.x = fmaxf((acc[mf][nf][2] + h1.x) * ri1, 0.f) + bz0;
            w1.y = fmaxf((acc[mf][nf][3] + h1.y) * ri1, 0.f) + bz1;
            *(float2*)(out + o0) = w0;
            *(float2*)(out + o1) = w1;
        }
    }
}

// ============================================================================
extern "C" void kernel_launch(void* const* d_in, const int* in_sizes, int n_in,
                              void* d_out, int out_size)
{
    const float* x    = (const float*)d_in[0];
    const float* adj  = (const float*)d_in[1];
    const float* wgt  = (const float*)d_in[2];
    const float* bias = (const float*)d_in[3];
    float* out = (float*)d_out;

    spconv_h_kernel<<<dim3(32, 8), 512>>>(x, wgt);
    spconv_gemm_kernel<<<dim3(64, 8), 256, SMEM_BYTES>>>(adj, bias, out);
}

// round 4
// speedup vs baseline: 3.4386x; 3.4386x over previous
#include <cuda_runtime.h>
#include <cuda_bf16.h>
#include <cstdint>

#define DEV_INLINE __device__ __forceinline__

constexpr int Bb = 8;
constexpr int Nn = 4096;

// ---------------- static device scratch (no allocation) ----------------
__device__ float    g_h32[Bb * Nn * 64];          // h fp32 (8 MB)
__device__ unsigned g_hpk_hi[Bb * (Nn/2) * 64];   // h hi bf16, node-pair packed
__device__ unsigned g_hpk_lo[Bb * (Nn/2) * 64];   // h lo residual (kept for possible reuse)

DEV_INLINE unsigned pack2(float f0, float f1) {   // f0 -> low 16 bits
    __nv_bfloat162 t = __floats2bfloat162_rn(f0, f1);
    return *reinterpret_cast<unsigned*>(&t);
}

// ============================================================================
// Kernel 1: h[b,n,j] = sum_{m,a} x[b,n,m,a]*W[m,p(j),a,w(j)]
// 128 threads: thread = (4-node group, p). acc[4][16]; W-LDS reused over 4
// nodes; node-pair bf16 packing entirely thread-local (no shfl).
// ============================================================================
__global__ void __launch_bounds__(128)
spconv_h_kernel(const float* __restrict__ x, const float* __restrict__ wgt)
{
    __shared__ float ws[128 * 64];   // ws[ka*64 + j],  j = p*16 + w
    const int t = threadIdx.x;
    const int b = blockIdx.y;
    const int ng = t >> 2;          // 0..31
    const int p  = t & 3;
    const int node0 = blockIdx.x * 128 + ng * 4;

    for (int idx = t; idx < 128 * 64; idx += 128) {
        int ka = idx >> 6, j = idx & 63;
        int m = ka >> 5, a = ka & 31, pp = j >> 4, w = j & 15;
        ws[idx] = wgt[(((m * 4 + pp) * 32 + a) << 4) + w];
    }
    __syncthreads();

    float acc[4][16];
#pragma unroll
    for (int nd = 0; nd < 4; nd++)
#pragma unroll
        for (int i = 0; i < 16; i++) acc[nd][i] = 0.f;

    const float* xr = x + (size_t)(b * Nn + node0) * 128;
#pragma unroll 1
    for (int ka4 = 0; ka4 < 32; ka4++) {
        float xa[4][4];
#pragma unroll
        for (int nd = 0; nd < 4; nd++) {
            float4 v = *(const float4*)(xr + nd * 128 + ka4 * 4);
            xa[nd][0] = v.x; xa[nd][1] = v.y; xa[nd][2] = v.z; xa[nd][3] = v.w;
        }
#pragma unroll
        for (int i = 0; i < 4; i++) {
            const float4* wr = (const float4*)&ws[(ka4 * 4 + i) * 64 + p * 16];
            float4 w0 = wr[0], w1 = wr[1], w2 = wr[2], w3 = wr[3];
#pragma unroll
            for (int nd = 0; nd < 4; nd++) {
                const float xs = xa[nd][i];
                acc[nd][ 0] = fmaf(xs, w0.x, acc[nd][ 0]);
                acc[nd][ 1] = fmaf(xs, w0.y, acc[nd][ 1]);
                acc[nd][ 2] = fmaf(xs, w0.z, acc[nd][ 2]);
                acc[nd][ 3] = fmaf(xs, w0.w, acc[nd][ 3]);
                acc[nd][ 4] = fmaf(xs, w1.x, acc[nd][ 4]);
                acc[nd][ 5] = fmaf(xs, w1.y, acc[nd][ 5]);
                acc[nd][ 6] = fmaf(xs, w1.z, acc[nd][ 6]);
                acc[nd][ 7] = fmaf(xs, w1.w, acc[nd][ 7]);
                acc[nd][ 8] = fmaf(xs, w2.x, acc[nd][ 8]);
                acc[nd][ 9] = fmaf(xs, w2.y, acc[nd][ 9]);
                acc[nd][10] = fmaf(xs, w2.z, acc[nd][10]);
                acc[nd][11] = fmaf(xs, w2.w, acc[nd][11]);
                acc[nd][12] = fmaf(xs, w3.x, acc[nd][12]);
                acc[nd][13] = fmaf(xs, w3.y, acc[nd][13]);
                acc[nd][14] = fmaf(xs, w3.z, acc[nd][14]);
                acc[nd][15] = fmaf(xs, w3.w, acc[nd][15]);
            }
        }
    }

    // fp32 h for epilogue
#pragma unroll
    for (int nd = 0; nd < 4; nd++) {
        float* hp = g_h32 + (size_t)(b * Nn + node0 + nd) * 64 + p * 16;
#pragma unroll
        for (int w4 = 0; w4 < 4; w4++)
            *(float4*)(hp + w4 * 4) = make_float4(acc[nd][w4*4+0], acc[nd][w4*4+1],
                                                  acc[nd][w4*4+2], acc[nd][w4*4+3]);
    }

    // node-pair packed bf16 hi/lo (pairs are thread-local)
#pragma unroll
    for (int pr = 0; pr < 2; pr++) {
        const size_t pb = ((size_t)(b * 2048 + (node0 >> 1) + pr)) * 64 + p * 16;
        unsigned hi[16], lo[16];
#pragma unroll
        for (int w = 0; w < 16; w++) {
            float v0 = acc[pr * 2 + 0][w];
            float v1 = acc[pr * 2 + 1][w];
            __nv_bfloat16 h0 = __float2bfloat16_rn(v0);
            __nv_bfloat16 h1 = __float2bfloat16_rn(v1);
            hi[w] = (unsigned)__bfloat16_as_ushort(h0)
                  | ((unsigned)__bfloat16_as_ushort(h1) << 16);
            lo[w] = pack2(v0 - __bfloat162float(h0), v1 - __bfloat162float(h1));
        }
#pragma unroll
        for (int w4 = 0; w4 < 4; w4++) {
            *(uint4*)(g_hpk_hi + pb + w4 * 4) = make_uint4(hi[w4*4], hi[w4*4+1], hi[w4*4+2], hi[w4*4+3]);
            *(uint4*)(g_hpk_lo + pb + w4 * 4) = make_uint4(lo[w4*4], lo[w4*4+1], lo[w4*4+2], lo[w4*4+3]);
        }
    }
}

// ============================================================================
// Kernel 2: per-batch C = adj @ h, fused rowsum/normalize/self-loop/relu/bias.
// 2-pass bf16 split (a_hi*b_hi + a_lo*b_hi). BM=128 BN=64 BK=32, 256 thr,
// warp tile 32x32. Double-buffered smem, ONE barrier per k-tile.
// ============================================================================
constexpr int A_STR = 20;                 // u32 per A row (16 kpairs + 4 pad)
constexpr int B_STR = 72;                 // u32 per B kpair row (64 + 8 pad)
constexpr int A_STAGE = 128 * A_STR;      // 2560
constexpr int B_STAGE = 16 * B_STR;       // 1152
constexpr int OFF_AH = 0;                      // 2 stages
constexpr int OFF_AL = 2 * A_STAGE;            // 5120
constexpr int OFF_BH = 4 * A_STAGE;            // 10240
constexpr int OFF_RS = OFF_BH + 2 * B_STAGE;   // 12544  (128*9 floats)
constexpr int OFF_RI = OFF_RS + 1152;          // 13696  (128 floats)
constexpr int SMEM_U32 = OFF_RI + 128;         // 13824
constexpr int SMEM_BYTES = SMEM_U32 * 4;       // 55296

DEV_INLINE void mma_bf16(float* c, const unsigned* a, const unsigned* b) {
    asm volatile(
        "mma.sync.aligned.m16n8k16.row.col.f32.bf16.bf16.f32 "
        "{%0,%1,%2,%3}, {%4,%5,%6,%7}, {%8,%9}, {%0,%1,%2,%3};\n"
        : "+f"(c[0]), "+f"(c[1]), "+f"(c[2]), "+f"(c[3])
        : "r"(a[0]), "r"(a[1]), "r"(a[2]), "r"(a[3]), "r"(b[0]), "r"(b[1]));
}

DEV_INLINE void ldsm4(unsigned* r, uint32_t addr) {
    asm volatile(
        "ldmatrix.sync.aligned.m8n8.x4.shared.b16 {%0,%1,%2,%3}, [%4];\n"
        : "=r"(r[0]), "=r"(r[1]), "=r"(r[2]), "=r"(r[3]) : "r"(addr));
}

__global__ void __launch_bounds__(256, 2)
spconv_gemm_kernel(const float* __restrict__ adj, const float* __restrict__ bias,
                   float* __restrict__ out)
{
    extern __shared__ unsigned sm[];
    const uint32_t smb = (uint32_t)__cvta_generic_to_shared(sm);

    const int t    = threadIdx.x;
    const int lane = t & 31, warp = t >> 5;
    const int g = lane >> 2, tg = lane & 3;
    const int wrow = warp >> 1, wcol = warp & 1;     // 4 x 2 warp grid
    const int bx = blockIdx.x, b = blockIdx.y;

    const int lm_row = (lane & 7) + ((lane >> 3) & 1) * 8;
    const int lm_kp  = ((lane >> 4) & 1) * 4;

    // A staging: thread loads rows (t>>3)+32p, cols (t&7)*4..+3  (coalesced)
    const int ar = t >> 3, ac4 = (t & 7) * 4, akp = (t & 7) * 2;
    const float* adj_base = adj + ((size_t)(b * Nn) + (size_t)bx * 128 + ar) * Nn + ac4;
    // B staging (hi only): kpair = t>>4, 4 u32 columns
    const int bkp = t >> 4, bn4 = (t & 15) * 4;
    const unsigned* hpH = g_hpk_hi + (size_t)b * 2048 * 64 + bkp * 64 + bn4;

    float acc[2][4][4];
#pragma unroll
    for (int mf = 0; mf < 2; mf++)
#pragma unroll
        for (int nf = 0; nf < 4; nf++)
#pragma unroll
            for (int i = 0; i < 4; i++) acc[mf][nf][i] = 0.f;

    float rsum[4] = {0.f, 0.f, 0.f, 0.f};
    float4 va[4];
    uint4 vbh;

    auto ldgA = [&](int kt) {
#pragma unroll
        for (int p = 0; p < 4; p++)
            va[p] = *(const float4*)(adj_base + (size_t)(p * 32) * Nn + kt * 32);
    };
    auto ldgB = [&](int kt) {
        vbh = *(const uint4*)(hpH + (size_t)kt * 1024);
    };
    auto stsAll = [&](int s) {
        unsigned* Ah = sm + OFF_AH + s * A_STAGE;
        unsigned* Al = sm + OFF_AL + s * A_STAGE;
#pragma unroll
        for (int p = 0; p < 4; p++) {
            float4 v = va[p];
            rsum[p] += (v.x + v.y) + (v.z + v.w);
            __nv_bfloat16 c0 = __float2bfloat16_rn(v.x);
            __nv_bfloat16 c1 = __float2bfloat16_rn(v.y);
            __nv_bfloat16 c2 = __float2bfloat16_rn(v.z);
            __nv_bfloat16 c3 = __float2bfloat16_rn(v.w);
            unsigned h0 = (unsigned)__bfloat16_as_ushort(c0)
                        | ((unsigned)__bfloat16_as_ushort(c1) << 16);
            unsigned h1 = (unsigned)__bfloat16_as_ushort(c2)
                        | ((unsigned)__bfloat16_as_ushort(c3) << 16);
            unsigned l0 = pack2(v.x - __bfloat162float(c0), v.y - __bfloat162float(c1));
            unsigned l1 = pack2(v.z - __bfloat162float(c2), v.w - __bfloat162float(c3));
            int idx = (ar + 32 * p) * A_STR + akp;
            *(uint2*)(Ah + idx) = make_uint2(h0, h1);
            *(uint2*)(Al + idx) = make_uint2(l0, l1);
        }
        *(uint4*)(sm + OFF_BH + s * B_STAGE + bkp * B_STR + bn4) = vbh;
    };
    auto compute = [&](int s) {
        const unsigned* Bh = sm + OFF_BH + s * B_STAGE;
        const uint32_t ahb = smb + (OFF_AH + s * A_STAGE) * 4;
        const uint32_t alb = smb + (OFF_AL + s * A_STAGE) * 4;
#pragma unroll
        for (int ks = 0; ks < 2; ks++) {
            unsigned bh[4][2];
#pragma unroll
            for (int nf = 0; nf < 4; nf++) {
                int n = wcol * 32 + nf * 8 + g;
                int k0 = (ks * 8 + tg) * B_STR + n;
                bh[nf][0] = Bh[k0];  bh[nf][1] = Bh[k0 + 4 * B_STR];
            }
#pragma unroll
            for (int mf = 0; mf < 2; mf++) {
                int aoff = ((wrow * 32 + mf * 16 + lm_row) * A_STR + ks * 8 + lm_kp) * 4;
                unsigned ah[4], al[4];
                ldsm4(ah, ahb + aoff);
                ldsm4(al, alb + aoff);
#pragma unroll
                for (int nf = 0; nf < 4; nf++) {
                    mma_bf16(acc[mf][nf], ah, bh[nf]);
                    mma_bf16(acc[mf][nf], al, bh[nf]);
                }
            }
        }
    };

    // ---- pipeline: one barrier per k-tile ----
    ldgA(0); ldgB(0);
    stsAll(0);
    __syncthreads();
#pragma unroll 1
    for (int kt = 0; kt < 128; kt++) {
        const int cur = kt & 1;
        if (kt < 127) { ldgA(kt + 1); ldgB(kt + 1); }
        compute(cur);
        if (kt < 127) {
            stsAll(1 - cur);
            __syncthreads();
        }
    }
    __syncthreads();

    // ---- rowsum reduce ----
    float* rs   = (float*)(sm + OFF_RS);   // [128][9]
    float* rinv = (float*)(sm + OFF_RI);   // [128]
#pragma unroll
    for (int p = 0; p < 4; p++) rs[(ar + 32 * p) * 9 + (t & 7)] = rsum[p];
    __syncthreads();
    if (t < 128) {
        float s_ = 1.0f;  // self loop
#pragma unroll
        for (int i = 0; i < 8; i++) s_ += rs[t * 9 + i];
        rinv[t] = 1.0f / s_;
    }
    __syncthreads();

    // ---- epilogue: out = relu((S + h)*rinv) + bias ----
#pragma unroll
    for (int mf = 0; mf < 2; mf++) {
#pragma unroll
        for (int nf = 0; nf < 4; nf++) {
            int r0 = wrow * 32 + mf * 16 + g;
            int c  = wcol * 32 + nf * 8 + 2 * tg;
            float ri0 = rinv[r0], ri1 = rinv[r0 + 8];
            int gr0 = bx * 128 + r0;
            size_t o0 = ((size_t)(b * Nn + gr0)) * 64 + c;
            size_t o1 = o0 + (size_t)8 * 64;
            float2 h0 = *(const float2*)(g_h32 + o0);
            float2 h1 = *(const float2*)(g_h32 + o1);
            float bz0 = __ldg(bias + c), bz1 = __ldg(bias + c + 1);
            float2 w0, w1;
            w0.x = fmaxf((acc[mf][nf][0] + h0.x) * ri0, 0.f) + bz0;
            w0.y = fmaxf((acc[mf][nf][1] + h0.y) * ri0, 0.f) + bz1;
            w1.x = fmaxf((acc[mf][nf][2] + h1.x) * ri1, 0.f) + bz0;
            w1.y = fmaxf((acc[mf][nf][3] + h1.y) * ri1, 0.f) + bz1;
            *(float2*)(out + o0) = w0;
            *(float2*)(out + o1) = w1;
        }
    }
}

// ============================================================================
extern "C" void kernel_launch(void* const* d_in, const int* in_sizes, int n_in,
                              void* d_out, int out_size)
{
    const float* x    = (const float*)d_in[0];
    const float* adj  = (const float*)d_in[1];
    const float* wgt  = (const float*)d_in[2];
    const float* bias = (const float*)d_in[3];
    float* out = (float*)d_out;

    cudaFuncSetAttribute(spconv_gemm_kernel,
                         cudaFuncAttributeMaxDynamicSharedMemorySize, SMEM_BYTES);

    spconv_h_kernel<<<dim3(32, 8), 128>>>(x, wgt);
    spconv_gemm_kernel<<<dim3(32, 8), 256, SMEM_BYTES>>>(adj, bias, out);
}